// round 5
// baseline (speedup 1.0000x reference)
#include <cuda_runtime.h>
#include <cstdint>

// x: [B, C, L, L] fp32, B=128, C=3, L=256, N=4 boxes per sample
// X/Y/W/H: [N, B] int32
// out[b,c,y,x] = inside-any-box(b,y,x) ? 0 : x[b,c,y,x]
//
// Mask depends on (b, y, x) only — computed once per col-quad, applied to all
// 3 channels. Streaming loads (.cs, no reuse); default stores (let L2 coalesce
// the write stream). Aggregate R+W is ~93% of HBM spec — this kernel is at the
// duplex roofline; structure follows the best-measured R2 shape.

#define BB 128
#define CC 3
#define LL 256
#define NN 4

#define CH4   (LL * LL / 4)          // 16384 float4 per channel plane
#define TOT4  (BB * CH4)             // 2,097,152 sites

__global__ __launch_bounds__(512)
void masking_kernel(const float4* __restrict__ x4,
                    const int* __restrict__ Xb,
                    const int* __restrict__ Yb,
                    const int* __restrict__ Wb,
                    const int* __restrict__ Hb,
                    float4* __restrict__ out4)
{
    int i4 = blockIdx.x * blockDim.x + threadIdx.x;   // [0, TOT4), exact grid

    int inner = i4 & (CH4 - 1);       // position within one channel plane
    int b     = i4 >> 14;             // sample (CH4 = 2^14)
    int col   = (i4 & 63) << 2;       // first column of this quad
    int y     = (i4 >> 6) & (LL - 1);

    long base = (long)b * (CC * CH4) + inner;

    // Front-batch the 3 streaming loads so they overlap mask ALU.
    float4 v0 = __ldcs(&x4[base]);
    float4 v1 = __ldcs(&x4[base + CH4]);
    float4 v2 = __ldcs(&x4[base + 2 * CH4]);

    // 4-bit column mask via unsigned range checks:
    //   inside iff (unsigned)(y - ys) <= h  &&  (unsigned)(c - xs) <= w
    unsigned m = 0u;
#pragma unroll
    for (int n = 0; n < NN; n++) {
        int xs = __ldg(&Xb[n * BB + b]);
        int ys = __ldg(&Yb[n * BB + b]);
        unsigned w = (unsigned)__ldg(&Wb[n * BB + b]);
        unsigned h = (unsigned)__ldg(&Hb[n * BB + b]);
        if ((unsigned)(y - ys) <= h) {
            unsigned d0 = (unsigned)(col + 0 - xs);
            unsigned d1 = (unsigned)(col + 1 - xs);
            unsigned d2 = (unsigned)(col + 2 - xs);
            unsigned d3 = (unsigned)(col + 3 - xs);
            m |= (d0 <= w) ? 1u : 0u;
            m |= (d1 <= w) ? 2u : 0u;
            m |= (d2 <= w) ? 4u : 0u;
            m |= (d3 <= w) ? 8u : 0u;
        }
    }

    if (m & 1u) { v0.x = 0.0f; v1.x = 0.0f; v2.x = 0.0f; }
    if (m & 2u) { v0.y = 0.0f; v1.y = 0.0f; v2.y = 0.0f; }
    if (m & 4u) { v0.z = 0.0f; v1.z = 0.0f; v2.z = 0.0f; }
    if (m & 8u) { v0.w = 0.0f; v1.w = 0.0f; v2.w = 0.0f; }

    out4[base]           = v0;
    out4[base + CH4]     = v1;
    out4[base + 2 * CH4] = v2;
}

extern "C" void kernel_launch(void* const* d_in, const int* in_sizes, int n_in,
                              void* d_out, int out_size)
{
    const float4* x4 = (const float4*)d_in[0];
    const int* Xb = (const int*)d_in[1];
    const int* Yb = (const int*)d_in[2];
    const int* Wb = (const int*)d_in[3];
    const int* Hb = (const int*)d_in[4];
    float4* out4 = (float4*)d_out;

    const int threads = 512;
    const int blocks = TOT4 / threads;   // 4096, exact
    masking_kernel<<<blocks, threads>>>(x4, Xb, Yb, Wb, Hb, out4);
}

// round 6
// speedup vs baseline: 1.0072x; 1.0072x over previous
#include <cuda_runtime.h>
#include <cstdint>

// x: [B, C, L, L] fp32, B=128, C=3, L=256, N=4 boxes per sample
// X/Y/W/H: [N, B] int32
// out[b,c,y,x] = inside-any-box(b,y,x) ? 0 : x[b,c,y,x]
//
// Converged form (R2 shape): one thread per (b, y, col-quad), covering all 3
// channels. Streaming hints on BOTH loads and stores (measured +3% DRAM util
// vs default stores). Aggregate R+W stream = ~7.4 TB/s = ~93% of HBM spec —
// at the duplex roofline.

#define BB 128
#define CC 3
#define LL 256
#define NN 4

#define CH4   (LL * LL / 4)          // 16384 float4 per channel plane
#define TOT4  (BB * CH4)             // 2,097,152 sites

__global__ __launch_bounds__(256)
void masking_kernel(const float4* __restrict__ x4,
                    const int* __restrict__ Xb,
                    const int* __restrict__ Yb,
                    const int* __restrict__ Wb,
                    const int* __restrict__ Hb,
                    float4* __restrict__ out4)
{
    int i4 = blockIdx.x * blockDim.x + threadIdx.x;   // [0, TOT4), exact grid

    int inner = i4 & (CH4 - 1);       // position within one channel plane
    int b     = i4 >> 14;             // sample (CH4 = 2^14)
    int col   = (i4 & 63) << 2;       // first column of this quad
    int y     = (i4 >> 6) & (LL - 1);

    long base = (long)b * (CC * CH4) + inner;

    // Front-batch the 3 streaming loads so they overlap the mask ALU.
    float4 v0 = __ldcs(&x4[base]);
    float4 v1 = __ldcs(&x4[base + CH4]);
    float4 v2 = __ldcs(&x4[base + 2 * CH4]);

    // 4-bit column mask via unsigned range checks:
    //   inside iff (unsigned)(y - ys) <= h  &&  (unsigned)(c - xs) <= w
    unsigned m = 0u;
#pragma unroll
    for (int n = 0; n < NN; n++) {
        int xs = __ldg(&Xb[n * BB + b]);
        int ys = __ldg(&Yb[n * BB + b]);
        unsigned w = (unsigned)__ldg(&Wb[n * BB + b]);
        unsigned h = (unsigned)__ldg(&Hb[n * BB + b]);
        if ((unsigned)(y - ys) <= h) {
            unsigned d = (unsigned)(col - xs);
            m |= ((unsigned)(d + 0u) <= w) ? 1u : 0u;
            m |= ((unsigned)(d + 1u) <= w) ? 2u : 0u;
            m |= ((unsigned)(d + 2u) <= w) ? 4u : 0u;
            m |= ((unsigned)(d + 3u) <= w) ? 8u : 0u;
        }
    }

    if (m & 1u) { v0.x = 0.0f; v1.x = 0.0f; v2.x = 0.0f; }
    if (m & 2u) { v0.y = 0.0f; v1.y = 0.0f; v2.y = 0.0f; }
    if (m & 4u) { v0.z = 0.0f; v1.z = 0.0f; v2.z = 0.0f; }
    if (m & 8u) { v0.w = 0.0f; v1.w = 0.0f; v2.w = 0.0f; }

    __stcs(&out4[base],           v0);
    __stcs(&out4[base + CH4],     v1);
    __stcs(&out4[base + 2 * CH4], v2);
}

extern "C" void kernel_launch(void* const* d_in, const int* in_sizes, int n_in,
                              void* d_out, int out_size)
{
    const float4* x4 = (const float4*)d_in[0];
    const int* Xb = (const int*)d_in[1];
    const int* Yb = (const int*)d_in[2];
    const int* Wb = (const int*)d_in[3];
    const int* Hb = (const int*)d_in[4];
    float4* out4 = (float4*)d_out;

    const int threads = 256;
    const int blocks = TOT4 / threads;   // 8192, exact
    masking_kernel<<<blocks, threads>>>(x4, Xb, Yb, Wb, Hb, out4);
}

// round 7
// speedup vs baseline: 1.0082x; 1.0009x over previous
#include <cuda_runtime.h>
#include <cstdint>

// x: [B, C, L, L] fp32, B=128, C=3, L=256, N=4 boxes per sample
// X/Y/W/H: [N, B] int32
// out[b,c,y,x] = inside-any-box(b,y,x) ? 0 : x[b,c,y,x]
// Mask depends on (b, y, x) only — compute once, apply to all 3 channels.
//
// CONVERGED FORM (best measured across 6 rounds: 27.07us kernel, DRAM 68.2%,
// aggregate R+W ~7.4 TB/s = ~93% of HBM duplex spec). Structural variants all
// measured neutral or worse: 2-site MLP6 (27.17), mask-first branch (28.22),
// plain stores/512thr (28.03), unsigned-range mask (28.10).

#define BB 128
#define CC 3
#define LL 256
#define NN 4

// float4s per (b) per channel: L*L/4 = 16384
#define CH4   (LL * LL / 4)          // 16384
// threads total: B * CH4 = 2,097,152  (one thread covers 3 channels)
#define TOT4  (BB * CH4)

__global__ __launch_bounds__(256)
void masking_kernel(const float4* __restrict__ x4,
                    const int* __restrict__ Xb,
                    const int* __restrict__ Yb,
                    const int* __restrict__ Wb,
                    const int* __restrict__ Hb,
                    float4* __restrict__ out4)
{
    int i4 = blockIdx.x * blockDim.x + threadIdx.x;   // [0, TOT4), exact grid

    int inner = i4 & (CH4 - 1);       // y*64 + col4 within one channel plane
    int b     = i4 >> 14;             // sample index (CH4 = 2^14)
    int col   = (i4 & 63) << 2;       // first column of this quad
    int y     = (i4 >> 6) & (LL - 1);

    long base = (long)b * (CC * CH4) + inner;

    // Front-batch all 3 channel loads (MLP_p1 = 3), streaming hint (no reuse).
    float4 v0 = __ldcs(&x4[base]);
    float4 v1 = __ldcs(&x4[base + CH4]);
    float4 v2 = __ldcs(&x4[base + 2 * CH4]);

    // 4-bit column mask for cols [col, col+3], any of N boxes.
    unsigned m = 0u;
#pragma unroll
    for (int n = 0; n < NN; n++) {
        int xs = __ldg(&Xb[n * BB + b]);
        int ys = __ldg(&Yb[n * BB + b]);
        int w  = __ldg(&Wb[n * BB + b]);
        int h  = __ldg(&Hb[n * BB + b]);
        bool yin = (y >= ys) && (y <= ys + h);
        if (yin) {
            int xe = xs + w;
#pragma unroll
            for (int j = 0; j < 4; j++) {
                int c = col + j;
                m |= ((c >= xs) & (c <= xe)) ? (1u << j) : 0u;
            }
        }
    }

    if (m & 1u) { v0.x = 0.0f; v1.x = 0.0f; v2.x = 0.0f; }
    if (m & 2u) { v0.y = 0.0f; v1.y = 0.0f; v2.y = 0.0f; }
    if (m & 4u) { v0.z = 0.0f; v1.z = 0.0f; v2.z = 0.0f; }
    if (m & 8u) { v0.w = 0.0f; v1.w = 0.0f; v2.w = 0.0f; }

    __stcs(&out4[base],           v0);
    __stcs(&out4[base + CH4],     v1);
    __stcs(&out4[base + 2 * CH4], v2);
}

extern "C" void kernel_launch(void* const* d_in, const int* in_sizes, int n_in,
                              void* d_out, int out_size)
{
    const float4* x4 = (const float4*)d_in[0];
    const int* Xb = (const int*)d_in[1];
    const int* Yb = (const int*)d_in[2];
    const int* Wb = (const int*)d_in[3];
    const int* Hb = (const int*)d_in[4];
    float4* out4 = (float4*)d_out;

    const int threads = 256;
    const int blocks = TOT4 / threads;   // 8192, exact
    masking_kernel<<<blocks, threads>>>(x4, Xb, Yb, Wb, Hb, out4);
}